// round 1
// baseline (speedup 1.0000x reference)
#include <cuda_runtime.h>
#include <math.h>

#define B_ 8
#define T_ 2048
#define V_ 1024
#define C_ 128
#define NB2 64  // 2*NB

// ---------------- device scratch (no allocations allowed) ----------------
__device__ float g_wqkv[V_ * 3 * C_];       // (V, 384): [:,0:128]=q_w, [:,128:256]=k_w, [:,256:384]=v_w
__device__ float g_wo[V_ * C_];             // (V, 128): o_w
__device__ float g_qkv[B_ * T_ * 3 * C_];   // (B*T, 384)
__device__ float g_r[B_ * T_ * C_];         // retrieved (B*T, 128)

// ---------------- 1) weights: basis @ coeffs^T (+ softmax over V) ----------------
// grid: (C_, 4), block: 1024 (one thread per vocab row)
__global__ void weights_kernel(const float* __restrict__ basis,
                               const float* __restrict__ qc,
                               const float* __restrict__ kc,
                               const float* __restrict__ vc,
                               const float* __restrict__ oc) {
    const int c = blockIdx.x;   // output channel
    const int w = blockIdx.y;   // 0=q 1=k 2=v 3=o
    const int v = threadIdx.x;  // vocab row

    const float* coef = (w == 0 ? qc : (w == 1 ? kc : (w == 2 ? vc : oc))) + c * NB2;
    __shared__ float scoef[NB2];
    __shared__ float red[32];
    __shared__ float sval;
    if (v < NB2) scoef[v] = coef[v];
    __syncthreads();

    float s = 0.f;
    const float4* brow = (const float4*)(basis + (size_t)v * NB2);
    #pragma unroll
    for (int jj = 0; jj < NB2 / 4; jj++) {
        float4 bv = brow[jj];
        s = fmaf(bv.x, scoef[4 * jj + 0], s);
        s = fmaf(bv.y, scoef[4 * jj + 1], s);
        s = fmaf(bv.z, scoef[4 * jj + 2], s);
        s = fmaf(bv.w, scoef[4 * jj + 3], s);
    }

    if (w == 3) {  // o_w: no softmax
        g_wo[(size_t)v * C_ + c] = s;
        return;
    }

    // block max over 1024 threads
    float m = s;
    #pragma unroll
    for (int o = 16; o; o >>= 1) m = fmaxf(m, __shfl_xor_sync(0xffffffffu, m, o));
    if ((v & 31) == 0) red[v >> 5] = m;
    __syncthreads();
    if (v < 32) {
        float t = red[v];
        #pragma unroll
        for (int o = 16; o; o >>= 1) t = fmaxf(t, __shfl_xor_sync(0xffffffffu, t, o));
        if (v == 0) sval = t;
    }
    __syncthreads();
    float e = expf(s - sval);

    // block sum
    float su = e;
    #pragma unroll
    for (int o = 16; o; o >>= 1) su += __shfl_xor_sync(0xffffffffu, su, o);
    if ((v & 31) == 0) red[v >> 5] = su;
    __syncthreads();
    if (v < 32) {
        float t = red[v];
        #pragma unroll
        for (int o = 16; o; o >>= 1) t += __shfl_xor_sync(0xffffffffu, t, o);
        if (v == 0) sval = t;
    }
    __syncthreads();

    g_wqkv[(size_t)v * (3 * C_) + w * C_ + c] = e / sval;
}

// ---------------- 2) QKV GEMM: g_qkv = x (16384x1024) @ g_wqkv (1024x384) ----------------
// grid: (3, 128), block: 256. BM=BN=128, BK=8, 8x8 per thread.
__global__ __launch_bounds__(256) void qkv_gemm_kernel(const float* __restrict__ A) {
    constexpr int BM = 128, BN = 128, BK = 8, TM = 8, TN = 8;
    constexpr int K = V_;       // 1024
    constexpr int N = 3 * C_;   // 384
    __shared__ float As[BK][BM];
    __shared__ float Bs[BK][BN];

    const int bm = blockIdx.y * BM;
    const int bn = blockIdx.x * BN;
    const int tid = threadIdx.x;
    const int tcol = tid % 16;
    const int trow = tid / 16;
    const int aRow = tid / 2;           // 0..127
    const int aCol = (tid % 2) * 4;     // 0 or 4
    const int bRow = tid / 32;          // 0..7
    const int bCol = (tid % 32) * 4;

    float acc[TM][TN] = {};
    const float* Aptr = A + (size_t)(bm + aRow) * K + aCol;

    for (int k0 = 0; k0 < K; k0 += BK) {
        float4 a4 = *(const float4*)(Aptr + k0);
        As[aCol + 0][aRow] = a4.x;
        As[aCol + 1][aRow] = a4.y;
        As[aCol + 2][aRow] = a4.z;
        As[aCol + 3][aRow] = a4.w;
        float4 b4 = *(const float4*)(g_wqkv + (size_t)(k0 + bRow) * N + bn + bCol);
        *(float4*)&Bs[bRow][bCol] = b4;
        __syncthreads();
        #pragma unroll
        for (int kk = 0; kk < BK; kk++) {
            float ar[TM], br[TN];
            *(float4*)&ar[0] = *(const float4*)&As[kk][trow * TM];
            *(float4*)&ar[4] = *(const float4*)&As[kk][trow * TM + 4];
            *(float4*)&br[0] = *(const float4*)&Bs[kk][tcol * TN];
            *(float4*)&br[4] = *(const float4*)&Bs[kk][tcol * TN + 4];
            #pragma unroll
            for (int i = 0; i < TM; i++)
                #pragma unroll
                for (int j = 0; j < TN; j++)
                    acc[i][j] = fmaf(ar[i], br[j], acc[i][j]);
        }
        __syncthreads();
    }
    #pragma unroll
    for (int i = 0; i < TM; i++) {
        float* crow = g_qkv + (size_t)(bm + trow * TM + i) * N + bn;
        *(float4*)(crow + tcol * TN)     = make_float4(acc[i][0], acc[i][1], acc[i][2], acc[i][3]);
        *(float4*)(crow + tcol * TN + 4) = make_float4(acc[i][4], acc[i][5], acc[i][6], acc[i][7]);
    }
}

// ---------------- 3) recurrence ----------------
// grid: (B_, 16), block: 64 (2 warps). Warp owns one batch and 4 output dims d.
// Lane owns M[c=4*lane..4*lane+3][d0..d0+3] in registers. Per step:
//   retrieved[d] = sum_c q[c]*M[c,d]  (read BEFORE write), warp-shfl reduce over c
//   M = dec*M + k (outer) v
__global__ void recur_kernel(const float* __restrict__ decay_ptr) {
    const int b = blockIdx.x;
    const int warp = threadIdx.x >> 5;
    const int lane = threadIdx.x & 31;
    const int d0 = (blockIdx.y * 2 + warp) * 4;
    const float dec = 1.0f / (1.0f + expf(-decay_ptr[0]));

    const float* qkv = g_qkv + (size_t)b * T_ * (3 * C_);
    float* rout = g_r + (size_t)b * T_ * C_;
    const int cbase = lane * 4;

    float M[4][4] = {};
    // prefetch t=0
    float4 q4 = *(const float4*)(qkv + cbase);
    float4 k4 = *(const float4*)(qkv + C_ + cbase);
    float4 v4 = *(const float4*)(qkv + 2 * C_ + d0);

    for (int t = 0; t < T_; t++) {
        float qa[4] = {q4.x, q4.y, q4.z, q4.w};
        float ka[4] = {k4.x, k4.y, k4.z, k4.w};
        float va[4] = {v4.x, v4.y, v4.z, v4.w};

        // prefetch next step (clamped)
        const int tn = (t + 1 < T_) ? (t + 1) : t;
        const float* bnext = qkv + (size_t)tn * (3 * C_);
        q4 = *(const float4*)(bnext + cbase);
        k4 = *(const float4*)(bnext + C_ + cbase);
        v4 = *(const float4*)(bnext + 2 * C_ + d0);

        // read before write
        float p[4] = {0.f, 0.f, 0.f, 0.f};
        #pragma unroll
        for (int i = 0; i < 4; i++)
            #pragma unroll
            for (int j = 0; j < 4; j++)
                p[j] = fmaf(qa[i], M[i][j], p[j]);

        // state update
        #pragma unroll
        for (int i = 0; i < 4; i++)
            #pragma unroll
            for (int j = 0; j < 4; j++)
                M[i][j] = fmaf(dec, M[i][j], ka[i] * va[j]);

        // reduce over c (32 lanes)
        #pragma unroll
        for (int o = 16; o; o >>= 1) {
            p[0] += __shfl_down_sync(0xffffffffu, p[0], o);
            p[1] += __shfl_down_sync(0xffffffffu, p[1], o);
            p[2] += __shfl_down_sync(0xffffffffu, p[2], o);
            p[3] += __shfl_down_sync(0xffffffffu, p[3], o);
        }
        if (lane == 0)
            *(float4*)(rout + (size_t)t * C_ + d0) = make_float4(p[0], p[1], p[2], p[3]);
    }
}

// ---------------- 4) output GEMM: out = g_r (16384x128) @ g_wo^T (128x1024) * scale ----------------
// grid: (8, 128), block: 256.
__global__ __launch_bounds__(256) void out_gemm_kernel(float* __restrict__ Cout,
                                                       const float* __restrict__ scale_ptr) {
    constexpr int BM = 128, BN = 128, BK = 8, TM = 8, TN = 8;
    constexpr int K = C_;   // 128
    constexpr int N = V_;   // 1024
    __shared__ float As[BK][BM];
    __shared__ float Bs[BK][BN];

    const int bm = blockIdx.y * BM;
    const int bn = blockIdx.x * BN;
    const int tid = threadIdx.x;
    const int tcol = tid % 16;
    const int trow = tid / 16;
    const int aRow = tid / 2;        // 0..127 (reused for both operands, both K-contiguous)
    const int aCol = (tid % 2) * 4;  // 0 or 4

    float acc[TM][TN] = {};

    for (int k0 = 0; k0 < K; k0 += BK) {
        float4 a4 = *(const float4*)(g_r + (size_t)(bm + aRow) * K + k0 + aCol);
        As[aCol + 0][aRow] = a4.x;
        As[aCol + 1][aRow] = a4.y;
        As[aCol + 2][aRow] = a4.z;
        As[aCol + 3][aRow] = a4.w;
        float4 b4 = *(const float4*)(g_wo + (size_t)(bn + aRow) * K + k0 + aCol);
        Bs[aCol + 0][aRow] = b4.x;
        Bs[aCol + 1][aRow] = b4.y;
        Bs[aCol + 2][aRow] = b4.z;
        Bs[aCol + 3][aRow] = b4.w;
        __syncthreads();
        #pragma unroll
        for (int kk = 0; kk < BK; kk++) {
            float ar[TM], br[TN];
            *(float4*)&ar[0] = *(const float4*)&As[kk][trow * TM];
            *(float4*)&ar[4] = *(const float4*)&As[kk][trow * TM + 4];
            *(float4*)&br[0] = *(const float4*)&Bs[kk][tcol * TN];
            *(float4*)&br[4] = *(const float4*)&Bs[kk][tcol * TN + 4];
            #pragma unroll
            for (int i = 0; i < TM; i++)
                #pragma unroll
                for (int j = 0; j < TN; j++)
                    acc[i][j] = fmaf(ar[i], br[j], acc[i][j]);
        }
        __syncthreads();
    }

    const float sc = *scale_ptr;
    #pragma unroll
    for (int i = 0; i < TM; i++) {
        float* crow = Cout + (size_t)(bm + trow * TM + i) * N + bn;
        *(float4*)(crow + tcol * TN) =
            make_float4(acc[i][0] * sc, acc[i][1] * sc, acc[i][2] * sc, acc[i][3] * sc);
        *(float4*)(crow + tcol * TN + 4) =
            make_float4(acc[i][4] * sc, acc[i][5] * sc, acc[i][6] * sc, acc[i][7] * sc);
    }
}

// ---------------- launch ----------------
extern "C" void kernel_launch(void* const* d_in, const int* in_sizes, int n_in,
                              void* d_out, int out_size) {
    const float* x      = (const float*)d_in[0];
    const float* basis  = (const float*)d_in[1];
    const float* qc     = (const float*)d_in[2];
    const float* kc     = (const float*)d_in[3];
    const float* vc     = (const float*)d_in[4];
    const float* oc     = (const float*)d_in[5];
    const float* decay  = (const float*)d_in[6];
    const float* oscale = (const float*)d_in[7];
    float* out = (float*)d_out;

    weights_kernel<<<dim3(C_, 4), 1024>>>(basis, qc, kc, vc, oc);
    qkv_gemm_kernel<<<dim3(3, (B_ * T_) / 128), 256>>>(x);
    recur_kernel<<<dim3(B_, 16), 64>>>(decay);
    out_gemm_kernel<<<dim3(V_ / 128, (B_ * T_) / 128), 256>>>(out, oscale);
}

// round 2
// speedup vs baseline: 1.9900x; 1.9900x over previous
#include <cuda_runtime.h>
#include <math.h>

#define B_ 8
#define T_ 2048
#define V_ 1024
#define C_ 128
#define NB2 64   // 2*NB
#define S_ 64    // chunk size
#define NCH 32   // T_/S_

// ---------------- device scratch ----------------
__device__ float g_wqkv[V_ * 3 * C_];       // (V, 384)
__device__ float g_wo[V_ * C_];             // (V, 128)
__device__ float g_qkv[B_ * T_ * 3 * C_];   // (B*T, 384)
__device__ float g_r[B_ * T_ * C_];         // retrieved (B*T, 128)
__device__ float g_G[B_ * NCH * C_ * C_];   // per-chunk outer-product sums
__device__ float g_M[B_ * NCH * C_ * C_];   // chunk-boundary states

__device__ __forceinline__ float sigmoidf_(float x) { return 1.0f / (1.0f + expf(-x)); }

// ---------------- 1) weights: basis @ coeffs^T (+ softmax over V) ----------------
__global__ void weights_kernel(const float* __restrict__ basis,
                               const float* __restrict__ qc,
                               const float* __restrict__ kc,
                               const float* __restrict__ vc,
                               const float* __restrict__ oc) {
    const int c = blockIdx.x;
    const int w = blockIdx.y;
    const int v = threadIdx.x;

    const float* coef = (w == 0 ? qc : (w == 1 ? kc : (w == 2 ? vc : oc))) + c * NB2;
    __shared__ float scoef[NB2];
    __shared__ float red[32];
    __shared__ float sval;
    if (v < NB2) scoef[v] = coef[v];
    __syncthreads();

    float s = 0.f;
    const float4* brow = (const float4*)(basis + (size_t)v * NB2);
    #pragma unroll
    for (int jj = 0; jj < NB2 / 4; jj++) {
        float4 bv = brow[jj];
        s = fmaf(bv.x, scoef[4 * jj + 0], s);
        s = fmaf(bv.y, scoef[4 * jj + 1], s);
        s = fmaf(bv.z, scoef[4 * jj + 2], s);
        s = fmaf(bv.w, scoef[4 * jj + 3], s);
    }

    if (w == 3) { g_wo[(size_t)v * C_ + c] = s; return; }

    float m = s;
    #pragma unroll
    for (int o = 16; o; o >>= 1) m = fmaxf(m, __shfl_xor_sync(0xffffffffu, m, o));
    if ((v & 31) == 0) red[v >> 5] = m;
    __syncthreads();
    if (v < 32) {
        float t = red[v];
        #pragma unroll
        for (int o = 16; o; o >>= 1) t = fmaxf(t, __shfl_xor_sync(0xffffffffu, t, o));
        if (v == 0) sval = t;
    }
    __syncthreads();
    float e = expf(s - sval);

    float su = e;
    #pragma unroll
    for (int o = 16; o; o >>= 1) su += __shfl_xor_sync(0xffffffffu, su, o);
    if ((v & 31) == 0) red[v >> 5] = su;
    __syncthreads();
    if (v < 32) {
        float t = red[v];
        #pragma unroll
        for (int o = 16; o; o >>= 1) t += __shfl_xor_sync(0xffffffffu, t, o);
        if (v == 0) sval = t;
    }
    __syncthreads();

    g_wqkv[(size_t)v * (3 * C_) + w * C_ + c] = e / sval;
}

// ---------------- 2) QKV GEMM ----------------
__global__ __launch_bounds__(256) void qkv_gemm_kernel(const float* __restrict__ A) {
    constexpr int BM = 128, BN = 128, BK = 8, TM = 8, TN = 8;
    constexpr int K = V_;
    constexpr int N = 3 * C_;
    __shared__ float As[BK][BM];
    __shared__ float Bs[BK][BN];

    const int bm = blockIdx.y * BM;
    const int bn = blockIdx.x * BN;
    const int tid = threadIdx.x;
    const int tcol = tid % 16;
    const int trow = tid / 16;
    const int aRow = tid / 2;
    const int aCol = (tid % 2) * 4;
    const int bRow = tid / 32;
    const int bCol = (tid % 32) * 4;

    float acc[TM][TN] = {};
    const float* Aptr = A + (size_t)(bm + aRow) * K + aCol;

    for (int k0 = 0; k0 < K; k0 += BK) {
        float4 a4 = *(const float4*)(Aptr + k0);
        As[aCol + 0][aRow] = a4.x;
        As[aCol + 1][aRow] = a4.y;
        As[aCol + 2][aRow] = a4.z;
        As[aCol + 3][aRow] = a4.w;
        float4 b4 = *(const float4*)(g_wqkv + (size_t)(k0 + bRow) * N + bn + bCol);
        *(float4*)&Bs[bRow][bCol] = b4;
        __syncthreads();
        #pragma unroll
        for (int kk = 0; kk < BK; kk++) {
            float ar[TM], br[TN];
            *(float4*)&ar[0] = *(const float4*)&As[kk][trow * TM];
            *(float4*)&ar[4] = *(const float4*)&As[kk][trow * TM + 4];
            *(float4*)&br[0] = *(const float4*)&Bs[kk][tcol * TN];
            *(float4*)&br[4] = *(const float4*)&Bs[kk][tcol * TN + 4];
            #pragma unroll
            for (int i = 0; i < TM; i++)
                #pragma unroll
                for (int j = 0; j < TN; j++)
                    acc[i][j] = fmaf(ar[i], br[j], acc[i][j]);
        }
        __syncthreads();
    }
    #pragma unroll
    for (int i = 0; i < TM; i++) {
        float* crow = g_qkv + (size_t)(bm + trow * TM + i) * N + bn;
        *(float4*)(crow + tcol * TN)     = make_float4(acc[i][0], acc[i][1], acc[i][2], acc[i][3]);
        *(float4*)(crow + tcol * TN + 4) = make_float4(acc[i][4], acc[i][5], acc[i][6], acc[i][7]);
    }
}

// ---------------- 3a) per-chunk outer-product sums G_j = sum_i d^{S-1-i} k_i v_i^T ----------------
// grid: (4 colgroups, NCH, B), block 256. Tile: G[128 x 32].
__global__ __launch_bounds__(256) void chunk_g_kernel(const float* __restrict__ decay_ptr) {
    const int cg = blockIdx.x;          // d0 = cg*32
    const int j  = blockIdx.y;
    const int b  = blockIdx.z;
    const float dec = sigmoidf_(decay_ptr[0]);
    const float l2d = log2f(dec);

    __shared__ float Ks[32][128];   // [ii][c] scaled
    __shared__ float Vs[32][32];    // [ii][dd]

    const int tid = threadIdx.x;
    const int trow = tid >> 3;      // 0..31 -> c rows 4*trow
    const int tcol = tid & 7;       // 0..7  -> d cols 4*tcol
    const int r  = tid >> 3;        // load row
    const int q8 = tid & 7;

    float acc[4][4] = {};
    const float* base = g_qkv + ((size_t)b * T_ + (size_t)j * S_) * (3 * C_);

    #pragma unroll
    for (int i0 = 0; i0 < S_; i0 += 32) {
        const float sc = exp2f((float)(S_ - 1 - (i0 + r)) * l2d);
        const float* krow = base + (size_t)(i0 + r) * (3 * C_) + C_;
        #pragma unroll
        for (int u = 0; u < 4; u++) {
            float4 kv = *(const float4*)(krow + (q8 + u * 8) * 4);
            Ks[r][(q8 + u * 8) * 4 + 0] = kv.x * sc;
            Ks[r][(q8 + u * 8) * 4 + 1] = kv.y * sc;
            Ks[r][(q8 + u * 8) * 4 + 2] = kv.z * sc;
            Ks[r][(q8 + u * 8) * 4 + 3] = kv.w * sc;
        }
        *(float4*)&Vs[r][q8 * 4] =
            *(const float4*)(base + (size_t)(i0 + r) * (3 * C_) + 2 * C_ + cg * 32 + q8 * 4);
        __syncthreads();
        #pragma unroll
        for (int ii = 0; ii < 32; ii++) {
            float4 a4 = *(const float4*)&Ks[ii][trow * 4];
            float4 b4 = *(const float4*)&Vs[ii][tcol * 4];
            float ar[4] = {a4.x, a4.y, a4.z, a4.w};
            float br[4] = {b4.x, b4.y, b4.z, b4.w};
            #pragma unroll
            for (int m = 0; m < 4; m++)
                #pragma unroll
                for (int n = 0; n < 4; n++)
                    acc[m][n] = fmaf(ar[m], br[n], acc[m][n]);
        }
        __syncthreads();
    }

    float* gout = g_G + ((size_t)(b * NCH + j) * C_ * C_) + cg * 32;
    #pragma unroll
    for (int m = 0; m < 4; m++)
        *(float4*)(gout + (size_t)(trow * 4 + m) * C_ + tcol * 4) =
            make_float4(acc[m][0], acc[m][1], acc[m][2], acc[m][3]);
}

// ---------------- 3b) scan: M_0 = 0; M_{j+1} = d^S M_j + G_j ----------------
// 32768 threads, each one float4 lane of (b, c, d) across all chunks.
__global__ void scan_kernel(const float* __restrict__ decay_ptr) {
    const int idx = blockIdx.x * blockDim.x + threadIdx.x;  // 0..32767
    const int b = idx >> 12;          // / 4096
    const int e4 = idx & 4095;
    const float dec = sigmoidf_(decay_ptr[0]);
    const float dS = exp2f((float)S_ * log2f(dec));

    const float4* G = (const float4*)(g_G + (size_t)b * NCH * C_ * C_) + e4;
    float4* M = (float4*)(g_M + (size_t)b * NCH * C_ * C_) + e4;

    float4 m = make_float4(0.f, 0.f, 0.f, 0.f);
    #pragma unroll
    for (int j = 0; j < NCH; j++) {
        M[(size_t)j * 4096] = m;
        float4 g = G[(size_t)j * 4096];
        m.x = fmaf(dS, m.x, g.x);
        m.y = fmaf(dS, m.y, g.y);
        m.z = fmaf(dS, m.z, g.z);
        m.w = fmaf(dS, m.w, g.w);
    }
}

// ---------------- 3c) retrieval per chunk ----------------
// grid: (NCH, B), block 256.
// R = maskedDecay(Q K^T) @ V + diag(d^i) (Q @ M_j)
__global__ __launch_bounds__(256) void retr_kernel(const float* __restrict__ decay_ptr) {
    const int j = blockIdx.x;
    const int b = blockIdx.y;
    const float dec = sigmoidf_(decay_ptr[0]);
    const float l2d = log2f(dec);

    __shared__ float Qs[32][64];    // [c][i]
    __shared__ float Ks2[32][64];   // [c][s]
    __shared__ float As[64][64];    // [s][i]  (A transposed)
    __shared__ float Vs[32][128];   // [s][d] / [c][d]

    const int tid = threadIdx.x;
    const float* base = g_qkv + ((size_t)b * T_ + (size_t)j * S_) * (3 * C_);

    // ---- phase 1: S_qk = Q K^T (64x64), thread 4x4 ----
    {
        const int ti = tid >> 4;    // 0..15 -> i rows
        const int ts = tid & 15;    // 0..15 -> s cols
        const int li = tid >> 2;    // load row 0..63
        const int lp = tid & 3;     // 0..3

        float acc[4][4] = {};
        for (int c0 = 0; c0 < C_; c0 += 32) {
            #pragma unroll
            for (int u = 0; u < 2; u++) {
                int c = lp * 8 + u * 4;
                float4 qv = *(const float4*)(base + (size_t)li * (3 * C_) + c0 + c);
                Qs[c + 0][li] = qv.x; Qs[c + 1][li] = qv.y;
                Qs[c + 2][li] = qv.z; Qs[c + 3][li] = qv.w;
                float4 kv = *(const float4*)(base + (size_t)li * (3 * C_) + C_ + c0 + c);
                Ks2[c + 0][li] = kv.x; Ks2[c + 1][li] = kv.y;
                Ks2[c + 2][li] = kv.z; Ks2[c + 3][li] = kv.w;
            }
            __syncthreads();
            #pragma unroll
            for (int cc = 0; cc < 32; cc++) {
                float4 a4 = *(const float4*)&Qs[cc][ti * 4];
                float4 b4 = *(const float4*)&Ks2[cc][ts * 4];
                float ar[4] = {a4.x, a4.y, a4.z, a4.w};
                float br[4] = {b4.x, b4.y, b4.z, b4.w};
                #pragma unroll
                for (int m = 0; m < 4; m++)
                    #pragma unroll
                    for (int n = 0; n < 4; n++)
                        acc[m][n] = fmaf(ar[m], br[n], acc[m][n]);
            }
            __syncthreads();
        }
        // mask + decay, store transposed As[s][i]
        #pragma unroll
        for (int m = 0; m < 4; m++) {
            const int i = ti * 4 + m;
            #pragma unroll
            for (int n = 0; n < 4; n++) {
                const int s = ts * 4 + n;
                float v = 0.f;
                if (s < i) v = acc[m][n] * exp2f((float)(i - 1 - s) * l2d);
                As[s][i] = v;
            }
        }
    }
    __syncthreads();

    // ---- phase 2: R = A@V + diag(d^i) Q@M ----
    const int ti2 = tid >> 4;   // 0..15 -> i rows (4 each)
    const int td  = tid & 15;   // 0..15 -> d cols (8 each)
    const int lr  = tid >> 3;   // load row 0..31
    const int lq  = tid & 7;

    float accA[4][8] = {};
    float accM[4][8] = {};

    // A @ V
    for (int s0 = 0; s0 < S_; s0 += 32) {
        #pragma unroll
        for (int u = 0; u < 4; u++) {
            int c4 = lq + u * 8;
            *(float4*)&Vs[lr][c4 * 4] =
                *(const float4*)(base + (size_t)(s0 + lr) * (3 * C_) + 2 * C_ + c4 * 4);
        }
        __syncthreads();
        #pragma unroll
        for (int ss = 0; ss < 32; ss++) {
            float4 a4 = *(const float4*)&As[s0 + ss][ti2 * 4];
            float4 b0 = *(const float4*)&Vs[ss][td * 8];
            float4 b1 = *(const float4*)&Vs[ss][td * 8 + 4];
            float ar[4] = {a4.x, a4.y, a4.z, a4.w};
            float br[8] = {b0.x, b0.y, b0.z, b0.w, b1.x, b1.y, b1.z, b1.w};
            #pragma unroll
            for (int m = 0; m < 4; m++)
                #pragma unroll
                for (int n = 0; n < 8; n++)
                    accA[m][n] = fmaf(ar[m], br[n], accA[m][n]);
        }
        __syncthreads();
    }

    // Q @ M
    const float* Mbase = g_M + (size_t)(b * NCH + j) * C_ * C_;
    {
        const int li = tid >> 2;
        const int lp = tid & 3;
        for (int c0 = 0; c0 < C_; c0 += 32) {
            #pragma unroll
            for (int u = 0; u < 2; u++) {
                int c = lp * 8 + u * 4;
                float4 qv = *(const float4*)(base + (size_t)li * (3 * C_) + c0 + c);
                Qs[c + 0][li] = qv.x; Qs[c + 1][li] = qv.y;
                Qs[c + 2][li] = qv.z; Qs[c + 3][li] = qv.w;
            }
            #pragma unroll
            for (int u = 0; u < 4; u++) {
                int c4 = lq + u * 8;
                *(float4*)&Vs[lr][c4 * 4] =
                    *(const float4*)(Mbase + (size_t)(c0 + lr) * C_ + c4 * 4);
            }
            __syncthreads();
            #pragma unroll
            for (int cc = 0; cc < 32; cc++) {
                float4 a4 = *(const float4*)&Qs[cc][ti2 * 4];
                float4 b0 = *(const float4*)&Vs[cc][td * 8];
                float4 b1 = *(const float4*)&Vs[cc][td * 8 + 4];
                float ar[4] = {a4.x, a4.y, a4.z, a4.w};
                float br[8] = {b0.x, b0.y, b0.z, b0.w, b1.x, b1.y, b1.z, b1.w};
                #pragma unroll
                for (int m = 0; m < 4; m++)
                    #pragma unroll
                    for (int n = 0; n < 8; n++)
                        accM[m][n] = fmaf(ar[m], br[n], accM[m][n]);
            }
            __syncthreads();
        }
    }

    // combine + write
    float* rout = g_r + ((size_t)b * T_ + (size_t)j * S_) * C_;
    #pragma unroll
    for (int m = 0; m < 4; m++) {
        const int i = ti2 * 4 + m;
        const float di = exp2f((float)i * l2d);
        float o[8];
        #pragma unroll
        for (int n = 0; n < 8; n++) o[n] = fmaf(di, accM[m][n], accA[m][n]);
        *(float4*)(rout + (size_t)i * C_ + td * 8)     = make_float4(o[0], o[1], o[2], o[3]);
        *(float4*)(rout + (size_t)i * C_ + td * 8 + 4) = make_float4(o[4], o[5], o[6], o[7]);
    }
}

// ---------------- 4) output GEMM: out = g_r @ g_wo^T * scale ----------------
__global__ __launch_bounds__(256) void out_gemm_kernel(float* __restrict__ Cout,
                                                       const float* __restrict__ scale_ptr) {
    constexpr int BM = 128, BN = 128, BK = 8, TM = 8, TN = 8;
    constexpr int K = C_;
    constexpr int N = V_;
    __shared__ float As[BK][BM];
    __shared__ float Bs[BK][BN];

    const int bm = blockIdx.y * BM;
    const int bn = blockIdx.x * BN;
    const int tid = threadIdx.x;
    const int tcol = tid % 16;
    const int trow = tid / 16;
    const int aRow = tid / 2;
    const int aCol = (tid % 2) * 4;

    float acc[TM][TN] = {};

    for (int k0 = 0; k0 < K; k0 += BK) {
        float4 a4 = *(const float4*)(g_r + (size_t)(bm + aRow) * K + k0 + aCol);
        As[aCol + 0][aRow] = a4.x;
        As[aCol + 1][aRow] = a4.y;
        As[aCol + 2][aRow] = a4.z;
        As[aCol + 3][aRow] = a4.w;
        float4 b4 = *(const float4*)(g_wo + (size_t)(bn + aRow) * K + k0 + aCol);
        Bs[aCol + 0][aRow] = b4.x;
        Bs[aCol + 1][aRow] = b4.y;
        Bs[aCol + 2][aRow] = b4.z;
        Bs[aCol + 3][aRow] = b4.w;
        __syncthreads();
        #pragma unroll
        for (int kk = 0; kk < BK; kk++) {
            float ar[TM], br[TN];
            *(float4*)&ar[0] = *(const float4*)&As[kk][trow * TM];
            *(float4*)&ar[4] = *(const float4*)&As[kk][trow * TM + 4];
            *(float4*)&br[0] = *(const float4*)&Bs[kk][tcol * TN];
            *(float4*)&br[4] = *(const float4*)&Bs[kk][tcol * TN + 4];
            #pragma unroll
            for (int i = 0; i < TM; i++)
                #pragma unroll
                for (int j = 0; j < TN; j++)
                    acc[i][j] = fmaf(ar[i], br[j], acc[i][j]);
        }
        __syncthreads();
    }

    const float sc = *scale_ptr;
    #pragma unroll
    for (int i = 0; i < TM; i++) {
        float* crow = Cout + (size_t)(bm + trow * TM + i) * N + bn;
        *(float4*)(crow + tcol * TN) =
            make_float4(acc[i][0] * sc, acc[i][1] * sc, acc[i][2] * sc, acc[i][3] * sc);
        *(float4*)(crow + tcol * TN + 4) =
            make_float4(acc[i][4] * sc, acc[i][5] * sc, acc[i][6] * sc, acc[i][7] * sc);
    }
}

// ---------------- launch ----------------
extern "C" void kernel_launch(void* const* d_in, const int* in_sizes, int n_in,
                              void* d_out, int out_size) {
    const float* x      = (const float*)d_in[0];
    const float* basis  = (const float*)d_in[1];
    const float* qc     = (const float*)d_in[2];
    const float* kc     = (const float*)d_in[3];
    const float* vc     = (const float*)d_in[4];
    const float* oc     = (const float*)d_in[5];
    const float* decay  = (const float*)d_in[6];
    const float* oscale = (const float*)d_in[7];
    float* out = (float*)d_out;

    weights_kernel<<<dim3(C_, 4), 1024>>>(basis, qc, kc, vc, oc);
    qkv_gemm_kernel<<<dim3(3, (B_ * T_) / 128), 256>>>(x);
    chunk_g_kernel<<<dim3(4, NCH, B_), 256>>>(decay);
    scan_kernel<<<128, 256>>>(decay);
    retr_kernel<<<dim3(NCH, B_), 256>>>(decay);
    out_gemm_kernel<<<dim3(V_ / 128, (B_ * T_) / 128), 256>>>(out, oscale);
}

// round 3
// speedup vs baseline: 3.0668x; 1.5411x over previous
#include <cuda_runtime.h>
#include <math.h>
#include <stdint.h>

#define B_ 8
#define T_ 2048
#define V_ 1024
#define C_ 128
#define NB2 64   // 2*NB
#define S_ 64    // chunk size
#define NCH 32   // T_/S_

// ---------------- device scratch ----------------
__device__ float g_wqkv[V_ * 3 * C_];       // (V, 384)
__device__ float g_qkv[B_ * T_ * 3 * C_];   // (B*T, 384)
__device__ float g_r[B_ * T_ * C_];         // retrieved (B*T, 128)
__device__ float g_r2[B_ * T_ * NB2];       // retrieved @ oc  (B*T, 64)
__device__ float g_G[B_ * NCH * C_ * C_];   // per-chunk outer-product sums
__device__ float g_M[B_ * NCH * C_ * C_];   // chunk-boundary states

__device__ __forceinline__ float sigmoidf_(float x) { return 1.0f / (1.0f + expf(-x)); }

__device__ __forceinline__ uint32_t f2tf32(float x) {
    uint32_t r;
    asm("cvt.rna.tf32.f32 %0, %1;" : "=r"(r) : "f"(x));
    return r;
}

__device__ __forceinline__ void mma_tf32(float* c, const uint32_t* a, const uint32_t* b) {
    asm volatile(
        "mma.sync.aligned.m16n8k8.row.col.f32.tf32.tf32.f32 "
        "{%0,%1,%2,%3}, {%4,%5,%6,%7}, {%8,%9}, {%0,%1,%2,%3};"
        : "+f"(c[0]), "+f"(c[1]), "+f"(c[2]), "+f"(c[3])
        : "r"(a[0]), "r"(a[1]), "r"(a[2]), "r"(a[3]), "r"(b[0]), "r"(b[1]));
}

// ---------------- 1) weights: basis @ coeffs^T (+ softmax over V), q/k/v only ----------------
__global__ void weights_kernel(const float* __restrict__ basis,
                               const float* __restrict__ qc,
                               const float* __restrict__ kc,
                               const float* __restrict__ vc) {
    const int c = blockIdx.x;
    const int w = blockIdx.y;   // 0=q 1=k 2=v
    const int v = threadIdx.x;

    const float* coef = (w == 0 ? qc : (w == 1 ? kc : vc)) + c * NB2;
    __shared__ float scoef[NB2];
    __shared__ float red[32];
    __shared__ float sval;
    if (v < NB2) scoef[v] = coef[v];
    __syncthreads();

    float s = 0.f;
    const float4* brow = (const float4*)(basis + (size_t)v * NB2);
    #pragma unroll
    for (int jj = 0; jj < NB2 / 4; jj++) {
        float4 bv = brow[jj];
        s = fmaf(bv.x, scoef[4 * jj + 0], s);
        s = fmaf(bv.y, scoef[4 * jj + 1], s);
        s = fmaf(bv.z, scoef[4 * jj + 2], s);
        s = fmaf(bv.w, scoef[4 * jj + 3], s);
    }

    float m = s;
    #pragma unroll
    for (int o = 16; o; o >>= 1) m = fmaxf(m, __shfl_xor_sync(0xffffffffu, m, o));
    if ((v & 31) == 0) red[v >> 5] = m;
    __syncthreads();
    if (v < 32) {
        float t = red[v];
        #pragma unroll
        for (int o = 16; o; o >>= 1) t = fmaxf(t, __shfl_xor_sync(0xffffffffu, t, o));
        if (v == 0) sval = t;
    }
    __syncthreads();
    float e = expf(s - sval);

    float su = e;
    #pragma unroll
    for (int o = 16; o; o >>= 1) su += __shfl_xor_sync(0xffffffffu, su, o);
    if ((v & 31) == 0) red[v >> 5] = su;
    __syncthreads();
    if (v < 32) {
        float t = red[v];
        #pragma unroll
        for (int o = 16; o; o >>= 1) t += __shfl_xor_sync(0xffffffffu, t, o);
        if (v == 0) sval = t;
    }
    __syncthreads();

    g_wqkv[(size_t)v * (3 * C_) + w * C_ + c] = e / sval;
}

// ---------------- 2) QKV GEMM via tensor cores (tf32 x3) ----------------
// g_qkv (16384x384) = x (16384x1024) @ g_wqkv (1024x384)
// BM=64, BN=64, BK=16, 128 threads (4 warps), warp tile 32x32.
__global__ __launch_bounds__(128) void qkv_mma_kernel(const float* __restrict__ A) {
    constexpr int K = V_;       // 1024
    constexpr int N = 3 * C_;   // 384
    __shared__ float As[2][64][20];   // [m][k], padded
    __shared__ float Bs[2][16][72];   // [k][n], padded

    const int tid = threadIdx.x;
    const int bm = blockIdx.y * 64;
    const int bn = blockIdx.x * 64;
    const int warp = tid >> 5;
    const int lane = tid & 31;
    const int g = lane >> 2;    // 0..7
    const int tg = lane & 3;    // 0..3
    const int wm = (warp >> 1) * 32;
    const int wn = (warp & 1) * 32;

    // ldg index mapping
    const int am = (tid * 2) >> 2;            // per t: idx = tid + t*128
    // (computed inline below)

    float c[2][4][4] = {};
    float4 ra[2], rb[2];

    // prologue: load k0=0 tile
    #pragma unroll
    for (int t = 0; t < 2; t++) {
        int idx = tid + t * 128;
        int m = idx >> 2, k4 = (idx & 3) * 4;
        ra[t] = *(const float4*)(A + (size_t)(bm + m) * K + k4);
        int kb = idx >> 4, n4 = (idx & 15) * 4;
        rb[t] = *(const float4*)(g_wqkv + (size_t)kb * N + bn + n4);
    }
    #pragma unroll
    for (int t = 0; t < 2; t++) {
        int idx = tid + t * 128;
        int m = idx >> 2, k4 = (idx & 3) * 4;
        *(float4*)&As[0][m][k4] = ra[t];
        int kb = idx >> 4, n4 = (idx & 15) * 4;
        *(float4*)&Bs[0][kb][n4] = rb[t];
    }
    __syncthreads();

    int buf = 0;
    for (int k0 = 0; k0 < K; k0 += 16) {
        const bool has_next = (k0 + 16 < K);
        if (has_next) {
            #pragma unroll
            for (int t = 0; t < 2; t++) {
                int idx = tid + t * 128;
                int m = idx >> 2, k4 = (idx & 3) * 4;
                ra[t] = *(const float4*)(A + (size_t)(bm + m) * K + k0 + 16 + k4);
                int kb = idx >> 4, n4 = (idx & 15) * 4;
                rb[t] = *(const float4*)(g_wqkv + (size_t)(k0 + 16 + kb) * N + bn + n4);
            }
        }

        #pragma unroll
        for (int kk8 = 0; kk8 < 16; kk8 += 8) {
            uint32_t a_hi[2][4], a_lo[2][4], b_hi[4][2], b_lo[4][2];
            #pragma unroll
            for (int mi = 0; mi < 2; mi++) {
                float x0 = As[buf][wm + mi * 16 + g][kk8 + tg];
                float x1 = As[buf][wm + mi * 16 + g + 8][kk8 + tg];
                float x2 = As[buf][wm + mi * 16 + g][kk8 + tg + 4];
                float x3 = As[buf][wm + mi * 16 + g + 8][kk8 + tg + 4];
                a_hi[mi][0] = f2tf32(x0); a_lo[mi][0] = f2tf32(x0 - __uint_as_float(a_hi[mi][0]));
                a_hi[mi][1] = f2tf32(x1); a_lo[mi][1] = f2tf32(x1 - __uint_as_float(a_hi[mi][1]));
                a_hi[mi][2] = f2tf32(x2); a_lo[mi][2] = f2tf32(x2 - __uint_as_float(a_hi[mi][2]));
                a_hi[mi][3] = f2tf32(x3); a_lo[mi][3] = f2tf32(x3 - __uint_as_float(a_hi[mi][3]));
            }
            #pragma unroll
            for (int ni = 0; ni < 4; ni++) {
                float y0 = Bs[buf][kk8 + tg][wn + ni * 8 + g];
                float y1 = Bs[buf][kk8 + tg + 4][wn + ni * 8 + g];
                b_hi[ni][0] = f2tf32(y0); b_lo[ni][0] = f2tf32(y0 - __uint_as_float(b_hi[ni][0]));
                b_hi[ni][1] = f2tf32(y1); b_lo[ni][1] = f2tf32(y1 - __uint_as_float(b_hi[ni][1]));
            }
            #pragma unroll
            for (int mi = 0; mi < 2; mi++)
                #pragma unroll
                for (int ni = 0; ni < 4; ni++) {
                    mma_tf32(c[mi][ni], a_lo[mi], b_hi[ni]);
                    mma_tf32(c[mi][ni], a_hi[mi], b_lo[ni]);
                    mma_tf32(c[mi][ni], a_hi[mi], b_hi[ni]);
                }
        }

        if (has_next) {
            #pragma unroll
            for (int t = 0; t < 2; t++) {
                int idx = tid + t * 128;
                int m = idx >> 2, k4 = (idx & 3) * 4;
                *(float4*)&As[buf ^ 1][m][k4] = ra[t];
                int kb = idx >> 4, n4 = (idx & 15) * 4;
                *(float4*)&Bs[buf ^ 1][kb][n4] = rb[t];
            }
        }
        __syncthreads();
        buf ^= 1;
    }

    // epilogue
    #pragma unroll
    for (int mi = 0; mi < 2; mi++) {
        #pragma unroll
        for (int ni = 0; ni < 4; ni++) {
            const int col = bn + wn + ni * 8 + tg * 2;
            const int r0 = bm + wm + mi * 16 + g;
            *(float2*)(g_qkv + (size_t)r0 * N + col)       = make_float2(c[mi][ni][0], c[mi][ni][1]);
            *(float2*)(g_qkv + (size_t)(r0 + 8) * N + col) = make_float2(c[mi][ni][2], c[mi][ni][3]);
        }
    }
}

// ---------------- 3a) per-chunk outer-product sums ----------------
__global__ __launch_bounds__(256) void chunk_g_kernel(const float* __restrict__ decay_ptr) {
    const int cg = blockIdx.x;
    const int j  = blockIdx.y;
    const int b  = blockIdx.z;
    const float dec = sigmoidf_(decay_ptr[0]);
    const float l2d = log2f(dec);

    __shared__ float Ks[32][128];
    __shared__ float Vs[32][32];

    const int tid = threadIdx.x;
    const int trow = tid >> 3;
    const int tcol = tid & 7;
    const int r  = tid >> 3;
    const int q8 = tid & 7;

    float acc[4][4] = {};
    const float* base = g_qkv + ((size_t)b * T_ + (size_t)j * S_) * (3 * C_);

    #pragma unroll
    for (int i0 = 0; i0 < S_; i0 += 32) {
        const float sc = exp2f((float)(S_ - 1 - (i0 + r)) * l2d);
        const float* krow = base + (size_t)(i0 + r) * (3 * C_) + C_;
        #pragma unroll
        for (int u = 0; u < 4; u++) {
            float4 kv = *(const float4*)(krow + (q8 + u * 8) * 4);
            Ks[r][(q8 + u * 8) * 4 + 0] = kv.x * sc;
            Ks[r][(q8 + u * 8) * 4 + 1] = kv.y * sc;
            Ks[r][(q8 + u * 8) * 4 + 2] = kv.z * sc;
            Ks[r][(q8 + u * 8) * 4 + 3] = kv.w * sc;
        }
        *(float4*)&Vs[r][q8 * 4] =
            *(const float4*)(base + (size_t)(i0 + r) * (3 * C_) + 2 * C_ + cg * 32 + q8 * 4);
        __syncthreads();
        #pragma unroll
        for (int ii = 0; ii < 32; ii++) {
            float4 a4 = *(const float4*)&Ks[ii][trow * 4];
            float4 b4 = *(const float4*)&Vs[ii][tcol * 4];
            float ar[4] = {a4.x, a4.y, a4.z, a4.w};
            float br[4] = {b4.x, b4.y, b4.z, b4.w};
            #pragma unroll
            for (int m = 0; m < 4; m++)
                #pragma unroll
                for (int n = 0; n < 4; n++)
                    acc[m][n] = fmaf(ar[m], br[n], acc[m][n]);
        }
        __syncthreads();
    }

    float* gout = g_G + ((size_t)(b * NCH + j) * C_ * C_) + cg * 32;
    #pragma unroll
    for (int m = 0; m < 4; m++)
        *(float4*)(gout + (size_t)(trow * 4 + m) * C_ + tcol * 4) =
            make_float4(acc[m][0], acc[m][1], acc[m][2], acc[m][3]);
}

// ---------------- 3b) scan with batched prefetch ----------------
__global__ void scan_kernel(const float* __restrict__ decay_ptr) {
    const int idx = blockIdx.x * blockDim.x + threadIdx.x;
    const int b = idx >> 12;
    const int e4 = idx & 4095;
    const float dec = sigmoidf_(decay_ptr[0]);
    const float dS = exp2f((float)S_ * log2f(dec));

    const float4* G = (const float4*)(g_G + (size_t)b * NCH * C_ * C_) + e4;
    float4* M = (float4*)(g_M + (size_t)b * NCH * C_ * C_) + e4;

    float4 m = make_float4(0.f, 0.f, 0.f, 0.f);
    #pragma unroll
    for (int jb = 0; jb < NCH; jb += 8) {
        float4 buf[8];
        #pragma unroll
        for (int u = 0; u < 8; u++) buf[u] = G[(size_t)(jb + u) * 4096];
        #pragma unroll
        for (int u = 0; u < 8; u++) {
            M[(size_t)(jb + u) * 4096] = m;
            m.x = fmaf(dS, m.x, buf[u].x);
            m.y = fmaf(dS, m.y, buf[u].y);
            m.z = fmaf(dS, m.z, buf[u].z);
            m.w = fmaf(dS, m.w, buf[u].w);
        }
    }
}

// ---------------- 3c) retrieval per chunk ----------------
__global__ __launch_bounds__(256) void retr_kernel(const float* __restrict__ decay_ptr) {
    const int j = blockIdx.x;
    const int b = blockIdx.y;
    const float dec = sigmoidf_(decay_ptr[0]);
    const float l2d = log2f(dec);

    __shared__ float Qs[32][64];
    __shared__ float Ks2[32][64];
    __shared__ float As[64][64];
    __shared__ float Vs[32][128];

    const int tid = threadIdx.x;
    const float* base = g_qkv + ((size_t)b * T_ + (size_t)j * S_) * (3 * C_);

    {
        const int ti = tid >> 4;
        const int ts = tid & 15;
        const int li = tid >> 2;
        const int lp = tid & 3;

        float acc[4][4] = {};
        for (int c0 = 0; c0 < C_; c0 += 32) {
            #pragma unroll
            for (int u = 0; u < 2; u++) {
                int c = lp * 8 + u * 4;
                float4 qv = *(const float4*)(base + (size_t)li * (3 * C_) + c0 + c);
                Qs[c + 0][li] = qv.x; Qs[c + 1][li] = qv.y;
                Qs[c + 2][li] = qv.z; Qs[c + 3][li] = qv.w;
                float4 kv = *(const float4*)(base + (size_t)li * (3 * C_) + C_ + c0 + c);
                Ks2[c + 0][li] = kv.x; Ks2[c + 1][li] = kv.y;
                Ks2[c + 2][li] = kv.z; Ks2[c + 3][li] = kv.w;
            }
            __syncthreads();
            #pragma unroll
            for (int cc = 0; cc < 32; cc++) {
                float4 a4 = *(const float4*)&Qs[cc][ti * 4];
                float4 b4 = *(const float4*)&Ks2[cc][ts * 4];
                float ar[4] = {a4.x, a4.y, a4.z, a4.w};
                float br[4] = {b4.x, b4.y, b4.z, b4.w};
                #pragma unroll
                for (int m = 0; m < 4; m++)
                    #pragma unroll
                    for (int n = 0; n < 4; n++)
                        acc[m][n] = fmaf(ar[m], br[n], acc[m][n]);
            }
            __syncthreads();
        }
        #pragma unroll
        for (int m = 0; m < 4; m++) {
            const int i = ti * 4 + m;
            #pragma unroll
            for (int n = 0; n < 4; n++) {
                const int s = ts * 4 + n;
                float v = 0.f;
                if (s < i) v = acc[m][n] * exp2f((float)(i - 1 - s) * l2d);
                As[s][i] = v;
            }
        }
    }
    __syncthreads();

    const int ti2 = tid >> 4;
    const int td  = tid & 15;
    const int lr  = tid >> 3;
    const int lq  = tid & 7;

    float accA[4][8] = {};
    float accM[4][8] = {};

    for (int s0 = 0; s0 < S_; s0 += 32) {
        #pragma unroll
        for (int u = 0; u < 4; u++) {
            int c4 = lq + u * 8;
            *(float4*)&Vs[lr][c4 * 4] =
                *(const float4*)(base + (size_t)(s0 + lr) * (3 * C_) + 2 * C_ + c4 * 4);
        }
        __syncthreads();
        #pragma unroll
        for (int ss = 0; ss < 32; ss++) {
            float4 a4 = *(const float4*)&As[s0 + ss][ti2 * 4];
            float4 b0 = *(const float4*)&Vs[ss][td * 8];
            float4 b1 = *(const float4*)&Vs[ss][td * 8 + 4];
            float ar[4] = {a4.x, a4.y, a4.z, a4.w};
            float br[8] = {b0.x, b0.y, b0.z, b0.w, b1.x, b1.y, b1.z, b1.w};
            #pragma unroll
            for (int m = 0; m < 4; m++)
                #pragma unroll
                for (int n = 0; n < 8; n++)
                    accA[m][n] = fmaf(ar[m], br[n], accA[m][n]);
        }
        __syncthreads();
    }

    const float* Mbase = g_M + (size_t)(b * NCH + j) * C_ * C_;
    {
        const int li = tid >> 2;
        const int lp = tid & 3;
        for (int c0 = 0; c0 < C_; c0 += 32) {
            #pragma unroll
            for (int u = 0; u < 2; u++) {
                int c = lp * 8 + u * 4;
                float4 qv = *(const float4*)(base + (size_t)li * (3 * C_) + c0 + c);
                Qs[c + 0][li] = qv.x; Qs[c + 1][li] = qv.y;
                Qs[c + 2][li] = qv.z; Qs[c + 3][li] = qv.w;
            }
            #pragma unroll
            for (int u = 0; u < 4; u++) {
                int c4 = lq + u * 8;
                *(float4*)&Vs[lr][c4 * 4] =
                    *(const float4*)(Mbase + (size_t)(c0 + lr) * C_ + c4 * 4);
            }
            __syncthreads();
            #pragma unroll
            for (int cc = 0; cc < 32; cc++) {
                float4 a4 = *(const float4*)&Qs[cc][ti2 * 4];
                float4 b0 = *(const float4*)&Vs[cc][td * 8];
                float4 b1 = *(const float4*)&Vs[cc][td * 8 + 4];
                float ar[4] = {a4.x, a4.y, a4.z, a4.w};
                float br[8] = {b0.x, b0.y, b0.z, b0.w, b1.x, b1.y, b1.z, b1.w};
                #pragma unroll
                for (int m = 0; m < 4; m++)
                    #pragma unroll
                    for (int n = 0; n < 8; n++)
                        accM[m][n] = fmaf(ar[m], br[n], accM[m][n]);
            }
            __syncthreads();
        }
    }

    float* rout = g_r + ((size_t)b * T_ + (size_t)j * S_) * C_;
    #pragma unroll
    for (int m = 0; m < 4; m++) {
        const int i = ti2 * 4 + m;
        const float di = exp2f((float)i * l2d);
        float o[8];
        #pragma unroll
        for (int n = 0; n < 8; n++) o[n] = fmaf(di, accM[m][n], accA[m][n]);
        *(float4*)(rout + (size_t)i * C_ + td * 8)     = make_float4(o[0], o[1], o[2], o[3]);
        *(float4*)(rout + (size_t)i * C_ + td * 8 + 4) = make_float4(o[4], o[5], o[6], o[7]);
    }
}

// ---------------- 4a) r2 = g_r (16384x128) @ oc (128x64) ----------------
__global__ __launch_bounds__(256) void oc_gemm_kernel(const float* __restrict__ oc) {
    constexpr int BK = 16;
    __shared__ float As[BK][C_];   // [k][m]
    __shared__ float Bs[BK][NB2];  // [k][n]

    const int tid = threadIdx.x;
    const int bm = blockIdx.x * 128;
    const int trow = tid >> 4;     // 0..15 -> rows trow*8
    const int tcol = tid & 15;     // 0..15 -> cols tcol*4

    float acc[8][4] = {};

    for (int k0 = 0; k0 < C_; k0 += BK) {
        // load A (128 rows x 16 k), transposed into As[k][m]
        #pragma unroll
        for (int t = 0; t < 2; t++) {
            int idx = tid + t * 256;          // 0..511
            int m = idx >> 2, k4 = (idx & 3) * 4;
            float4 a4 = *(const float4*)(g_r + (size_t)(bm + m) * C_ + k0 + k4);
            As[k4 + 0][m] = a4.x; As[k4 + 1][m] = a4.y;
            As[k4 + 2][m] = a4.z; As[k4 + 3][m] = a4.w;
        }
        // load B (16 k x 64 n)
        {
            int k = tid >> 4, n4 = (tid & 15) * 4;
            *(float4*)&Bs[k][n4] = *(const float4*)(oc + (size_t)(k0 + k) * NB2 + n4);
        }
        __syncthreads();
        #pragma unroll
        for (int kk = 0; kk < BK; kk++) {
            float ar[8], br[4];
            *(float4*)&ar[0] = *(const float4*)&As[kk][trow * 8];
            *(float4*)&ar[4] = *(const float4*)&As[kk][trow * 8 + 4];
            *(float4*)&br[0] = *(const float4*)&Bs[kk][tcol * 4];
            #pragma unroll
            for (int i = 0; i < 8; i++)
                #pragma unroll
                for (int jn = 0; jn < 4; jn++)
                    acc[i][jn] = fmaf(ar[i], br[jn], acc[i][jn]);
        }
        __syncthreads();
    }
    #pragma unroll
    for (int i = 0; i < 8; i++)
        *(float4*)(g_r2 + (size_t)(bm + trow * 8 + i) * NB2 + tcol * 4) =
            make_float4(acc[i][0], acc[i][1], acc[i][2], acc[i][3]);
}

// ---------------- 4b) out = g_r2 (16384x64) @ basis^T (64x1024) * scale ----------------
__global__ __launch_bounds__(256) void out2_gemm_kernel(float* __restrict__ Cout,
                                                        const float* __restrict__ basis,
                                                        const float* __restrict__ scale_ptr) {
    constexpr int BM = 128, BN = 128, BK = 8, TM = 8, TN = 8;
    constexpr int K = NB2;   // 64
    constexpr int N = V_;    // 1024
    __shared__ float As[BK][BM];
    __shared__ float Bs[BK][BN];

    const int bm = blockIdx.y * BM;
    const int bn = blockIdx.x * BN;
    const int tid = threadIdx.x;
    const int tcol = tid % 16;
    const int trow = tid / 16;
    const int aRow = tid / 2;
    const int aCol = (tid % 2) * 4;

    float acc[TM][TN] = {};

    for (int k0 = 0; k0 < K; k0 += BK) {
        float4 a4 = *(const float4*)(g_r2 + (size_t)(bm + aRow) * K + k0 + aCol);
        As[aCol + 0][aRow] = a4.x;
        As[aCol + 1][aRow] = a4.y;
        As[aCol + 2][aRow] = a4.z;
        As[aCol + 3][aRow] = a4.w;
        float4 b4 = *(const float4*)(basis + (size_t)(bn + aRow) * K + k0 + aCol);
        Bs[aCol + 0][aRow] = b4.x;
        Bs[aCol + 1][aRow] = b4.y;
        Bs[aCol + 2][aRow] = b4.z;
        Bs[aCol + 3][aRow] = b4.w;
        __syncthreads();
        #pragma unroll
        for (int kk = 0; kk < BK; kk++) {
            float ar[TM], br[TN];
            *(float4*)&ar[0] = *(const float4*)&As[kk][trow * TM];
            *(float4*)&ar[4] = *(const float4*)&As[kk][trow * TM + 4];
            *(float4*)&br[0] = *(const float4*)&Bs[kk][tcol * TN];
            *(float4*)&br[4] = *(const float4*)&Bs[kk][tcol * TN + 4];
            #pragma unroll
            for (int i = 0; i < TM; i++)
                #pragma unroll
                for (int jn = 0; jn < TN; jn++)
                    acc[i][jn] = fmaf(ar[i], br[jn], acc[i][jn]);
        }
        __syncthreads();
    }

    const float sc = *scale_ptr;
    #pragma unroll
    for (int i = 0; i < TM; i++) {
        float* crow = Cout + (size_t)(bm + trow * TM + i) * N + bn;
        *(float4*)(crow + tcol * TN) =
            make_float4(acc[i][0] * sc, acc[i][1] * sc, acc[i][2] * sc, acc[i][3] * sc);
        *(float4*)(crow + tcol * TN + 4) =
            make_float4(acc[i][4] * sc, acc[i][5] * sc, acc[i][6] * sc, acc[i][7] * sc);
    }
}

// ---------------- launch ----------------
extern "C" void kernel_launch(void* const* d_in, const int* in_sizes, int n_in,
                              void* d_out, int out_size) {
    const float* x      = (const float*)d_in[0];
    const float* basis  = (const float*)d_in[1];
    const float* qc     = (const float*)d_in[2];
    const float* kc     = (const float*)d_in[3];
    const float* vc     = (const float*)d_in[4];
    const float* oc     = (const float*)d_in[5];
    const float* decay  = (const float*)d_in[6];
    const float* oscale = (const float*)d_in[7];
    float* out = (float*)d_out;

    weights_kernel<<<dim3(C_, 3), 1024>>>(basis, qc, kc, vc);
    qkv_mma_kernel<<<dim3((3 * C_) / 64, (B_ * T_) / 64), 128>>>(x);
    chunk_g_kernel<<<dim3(4, NCH, B_), 256>>>(decay);
    scan_kernel<<<128, 256>>>(decay);
    retr_kernel<<<dim3(NCH, B_), 256>>>(decay);
    oc_gemm_kernel<<<(B_ * T_) / 128, 256>>>(oc);
    out2_gemm_kernel<<<dim3(V_ / 128, (B_ * T_) / 128), 256>>>(out, basis, oscale);
}